// round 14
// baseline (speedup 1.0000x reference)
#include <cuda_runtime.h>
#include <cstdint>

#define Dm 1024
#define Nn 64
#define Ne 1024

// ---------------- scratch (device globals; no allocations allowed) ----------------
__device__ float g_Xv[Nn * 4 * Dm];      // ld 4096: t0 [a,a,a^2,-]; t1 [a,c,ac,c-a] (fp32)
__device__ float g_vj[Nn * Dm];
__device__ float g_SO[Nn * 2 * Dm];      // [S | O], ld 2048
__device__ float g_QQ[Nn * 2 * Dm];      // [Qs | Qo], ld 2048
__device__ float g_QQ2[Nn * 2 * Dm];     // [Qs2 | Qo2], ld 2048
__device__ float g_Xr[Ne * 3 * Dm];      // ld 3072, tf32: t0 [r,r,r^2]; t1 [r,c,rc]
__device__ float g_rj[Ne * Dm];          // tf32
__device__ float g_relj[Ne * Dm];        // fp32
__device__ float g_Xrc2[2 * Ne * 2 * Dm];
__device__ float g_Xc[Nn * 3 * Dm];
__device__ float g_Xn[Nn * 2 * Dm];
__device__ float g_part[8 * Nn * 4 * Dm];
__device__ float g_WrB[Dm * 3072];       // [Wr1+Wr4 | Wr2-Wr4 | Wr3], tf32 (t1 only)
__device__ int g_src[Ne];
__device__ int g_dst[Ne];

__device__ __forceinline__ uint32_t f2tf32(float x) {
    uint32_t u;
    asm("cvt.rna.tf32.f32 %0, %1;" : "=r"(u) : "f"(x));
    return u;
}
__device__ __forceinline__ float rtf(float x) { return __uint_as_float(f2tf32(x)); }

__device__ __forceinline__ uint32_t smem_u32(const void* p) {
    uint32_t r;
    asm("{ .reg .u64 t; cvta.to.shared.u64 t, %1; cvt.u32.u64 %0, t; }" : "=r"(r) : "l"(p));
    return r;
}

// ---------------- init: data setup only (no weight folding) ----------------
__global__ void k_init(const float* __restrict__ v, const float* __restrict__ rel,
                       const int* __restrict__ eidx, float* __restrict__ xrcA) {
    int idx = blockIdx.x * 256 + threadIdx.x;
    int stride = gridDim.x * 256;
    for (int t = idx; t < Ne * Dm; t += stride) {
        int e = t >> 10, d = t & 1023;
        float r = rel[t];
        float rr = rtf(r);
        float* xr = g_Xr + (size_t)e * 3072;
        xr[d] = rr; xr[1024 + d] = rr; xr[2048 + d] = rtf(r * r);
        xrcA[(size_t)e * 2048 + d] = rr;
    }
    for (int t = idx; t < Nn * Dm; t += stride) {
        int i = t >> 10, d = t & 1023;
        float a = v[t];
        float* xv = g_Xv + (size_t)i * 4096;
        xv[d] = a; xv[1024 + d] = a; xv[2048 + d] = a * a;
        g_Xc[(size_t)i * 3072 + d] = a;
    }
    for (int t = idx; t < Ne; t += stride) {
        int e = eidx[t];
        g_src[t] = e >> 6;
        g_dst[t] = e & 63;
    }
}

// ---------------- fold WrB only (runs on s2, hidden behind t0 edge work) ----------
__global__ void k_foldB(const float* __restrict__ Wr) {
    int idx = blockIdx.x * 256 + threadIdx.x;
    if (idx >= Dm * Dm) return;
    int o = idx >> 10, d = idx & 1023;
    const float* r = Wr + (size_t)o * 4096;
    float w1 = r[d], w2 = r[1024 + d], w3 = r[2048 + d], w4 = r[3072 + d];
    g_WrB[(size_t)o * 3072 + d] = rtf(w1 + w4);
    g_WrB[(size_t)o * 3072 + 1024 + d] = rtf(w2 - w4);
    g_WrB[(size_t)o * 3072 + 2048 + d] = rtf(w3);
}

// ======================= tf32 tensor-core NT GEMM (cp.async, BK=32, 3-stage) ======
// A pre-rounded; B fragments cvt'd in-kernel (raw or pre-rounded B both fine).
// MODE 3: C rounded. MODE 0: C fp32.
// MODE 1: C += g_SO[src] + g_SO[dst + 1024] (f32); xrc 2nd half rounded.
// MODE 2: no C; flag==1 -> xrc relctx + Xr=[rel,ctx,rel*ctx] (ld 3072) rounded;
//         flag==2 -> final xrc=[rel, relctx] rounded.
#define TS 3
#define BK 32
#define APAD 36
#define A_STG (128 * APAD)
#define B_STG (64 * APAD)
#define SMEM_BYTES ((TS * A_STG + TS * B_STG) * 4)

template <int MODE>
__global__ void __launch_bounds__(256) k_tgemm(
    const float* __restrict__ A, int lda,
    const float* __restrict__ B, int ldb,
    float* __restrict__ C, int K,
    float* __restrict__ xrc_w, const float* __restrict__ rel, int flag) {
    extern __shared__ float smem[];
    float* As = smem;
    float* Bs = smem + TS * A_STG;

    int tid = threadIdx.x;
    int lane = tid & 31;
    int w = tid >> 5;
    int wm = (w & 3) * 32;
    int wn = (w >> 2) * 32;
    int gr = lane >> 2;
    int gc = lane & 3;

    const float* Ag = A + (size_t)(blockIdx.y * 128 + (tid >> 1)) * lda + (tid & 1) * 16;
    const float* Bg = B + (size_t)(blockIdx.x * 64 + (tid >> 2)) * ldb + (tid & 3) * 8;
    uint32_t a_dst = smem_u32(&As[(tid >> 1) * APAD + (tid & 1) * 16]);
    uint32_t b_dst = smem_u32(&Bs[(tid >> 2) * APAD + (tid & 3) * 8]);

    int niter = K >> 5;

#define ISSUE_STAGE(s, k0)                                                                   \
    do {                                                                                     \
        uint32_t ad = a_dst + (uint32_t)(s) * (A_STG * 4);                                   \
        const float* ap = Ag + (k0);                                                         \
        asm volatile("cp.async.cg.shared.global [%0], [%1], 16;" :: "r"(ad), "l"(ap));       \
        asm volatile("cp.async.cg.shared.global [%0], [%1], 16;" :: "r"(ad + 16), "l"(ap + 4)); \
        asm volatile("cp.async.cg.shared.global [%0], [%1], 16;" :: "r"(ad + 32), "l"(ap + 8)); \
        asm volatile("cp.async.cg.shared.global [%0], [%1], 16;" :: "r"(ad + 48), "l"(ap + 12)); \
        uint32_t bd = b_dst + (uint32_t)(s) * (B_STG * 4);                                   \
        const float* bp = Bg + (k0);                                                         \
        asm volatile("cp.async.cg.shared.global [%0], [%1], 16;" :: "r"(bd), "l"(bp));       \
        asm volatile("cp.async.cg.shared.global [%0], [%1], 16;" :: "r"(bd + 16), "l"(bp + 4)); \
    } while (0)

    ISSUE_STAGE(0, 0);
    asm volatile("cp.async.commit_group;");
    ISSUE_STAGE(1, BK);
    asm volatile("cp.async.commit_group;");

    float c[2][4][4];
#pragma unroll
    for (int mt = 0; mt < 2; ++mt)
#pragma unroll
        for (int nt = 0; nt < 4; ++nt)
#pragma unroll
            for (int q = 0; q < 4; ++q) c[mt][nt][q] = 0.f;

    const uint32_t* Asu = reinterpret_cast<const uint32_t*>(As);
    const float* Bsf = Bs;

    int s = 0;
    for (int i = 0; i < niter; ++i) {
        asm volatile("cp.async.wait_group 1;" ::: "memory");
        __syncthreads();
        {
            int nx = i + 2;
            if (nx < niter) {
                int sn = s + 2; if (sn >= TS) sn -= TS;
                ISSUE_STAGE(sn, nx * BK);
            }
            asm volatile("cp.async.commit_group;");
        }
        int base_a = s * A_STG;
        int base_b = s * B_STG;
#pragma unroll
        for (int half = 0; half < 2; ++half) {
            uint32_t a[2][2][4], b[2][4][2];
#pragma unroll
            for (int ks = 0; ks < 2; ++ks) {
                int kb = half * 16 + ks * 8 + gc;
#pragma unroll
                for (int mt = 0; mt < 2; ++mt) {
                    int m0 = wm + mt * 16 + gr;
                    a[ks][mt][0] = Asu[base_a + m0 * APAD + kb];
                    a[ks][mt][1] = Asu[base_a + (m0 + 8) * APAD + kb];
                    a[ks][mt][2] = Asu[base_a + m0 * APAD + kb + 4];
                    a[ks][mt][3] = Asu[base_a + (m0 + 8) * APAD + kb + 4];
                }
#pragma unroll
                for (int nt = 0; nt < 4; ++nt) {
                    int n0 = wn + nt * 8 + gr;
                    b[ks][nt][0] = f2tf32(Bsf[base_b + n0 * APAD + kb]);
                    b[ks][nt][1] = f2tf32(Bsf[base_b + n0 * APAD + kb + 4]);
                }
            }
#pragma unroll
            for (int ks = 0; ks < 2; ++ks)
#pragma unroll
                for (int mt = 0; mt < 2; ++mt)
#pragma unroll
                    for (int nt = 0; nt < 4; ++nt) {
                        asm volatile(
                            "mma.sync.aligned.m16n8k8.row.col.f32.tf32.tf32.f32 "
                            "{%0,%1,%2,%3}, {%4,%5,%6,%7}, {%8,%9}, {%0,%1,%2,%3};"
                            : "+f"(c[mt][nt][0]), "+f"(c[mt][nt][1]),
                              "+f"(c[mt][nt][2]), "+f"(c[mt][nt][3])
                            : "r"(a[ks][mt][0]), "r"(a[ks][mt][1]),
                              "r"(a[ks][mt][2]), "r"(a[ks][mt][3]),
                              "r"(b[ks][nt][0]), "r"(b[ks][nt][1]));
                    }
        }
        if (++s >= TS) s -= TS;
    }
#undef ISSUE_STAGE

    int mbase = blockIdx.y * 128 + wm;
    int nbase = blockIdx.x * 64 + wn;
#pragma unroll
    for (int mt = 0; mt < 2; ++mt) {
#pragma unroll
        for (int half = 0; half < 2; ++half) {
            int row = mbase + mt * 16 + gr + half * 8;
#pragma unroll
            for (int nt = 0; nt < 4; ++nt) {
                int col = nbase + nt * 8 + 2 * gc;
                float vx = c[mt][nt][half * 2 + 0];
                float vy = c[mt][nt][half * 2 + 1];
                if (MODE == 0) {
                    *(float2*)(C + (size_t)row * 1024 + col) = make_float2(vx, vy);
                } else if (MODE == 3) {
                    *(float2*)(C + (size_t)row * 1024 + col) = make_float2(rtf(vx), rtf(vy));
                } else if (MODE == 1) {
                    const float* sp = g_SO + (size_t)g_src[row] * 2048 + col;
                    const float* op = g_SO + (size_t)g_dst[row] * 2048 + 1024 + col;
                    vx += sp[0] + op[0];
                    vy += sp[1] + op[1];
                    *(float2*)(C + (size_t)row * 1024 + col) = make_float2(vx, vy);
                    *(float2*)(xrc_w + (size_t)row * 2048 + 1024 + col) =
                        make_float2(rtf(vx), rtf(vy));
                } else {  // MODE 2
                    float2 rv = *(const float2*)(rel + (size_t)row * 1024 + col);
                    if (flag == 1) {
                        *(float2*)(xrc_w + (size_t)row * 2048 + col) =
                            make_float2(rtf(vx), rtf(vy));
                        float* xr = g_Xr + (size_t)row * 3072;
                        *(float2*)(xr + col)        = make_float2(rtf(rv.x), rtf(rv.y));
                        *(float2*)(xr + 1024 + col) = make_float2(rtf(vx), rtf(vy));
                        *(float2*)(xr + 2048 + col) =
                            make_float2(rtf(rv.x * vx), rtf(rv.y * vy));
                    } else {
                        *(float2*)(xrc_w + (size_t)row * 2048 + col) =
                            make_float2(rtf(rv.x), rtf(rv.y));
                        *(float2*)(xrc_w + (size_t)row * 2048 + 1024 + col) =
                            make_float2(rtf(vx), rtf(vy));
                    }
                }
            }
        }
    }
}

// ---------------- FFMA NT GEMM, M=64, split-K, 4-region B select ----------------
__global__ void __launch_bounds__(128) k_gemm(
    const float* __restrict__ A, int lda,
    const float* __restrict__ B0, const float* __restrict__ B1,
    const float* __restrict__ B2, const float* __restrict__ B3,
    int ldb01, int ldb23,
    float* __restrict__ part, int ldc, size_t strideCz, int Kc) {
    __shared__ float As[16][64];
    __shared__ float Bs[16][128];
    int tid = threadIdx.x;
    int trow = tid >> 4;
    int tcol = tid & 15;
    int bx = blockIdx.x;
    int region = bx >> 3;
    const float* Bp = (region == 0) ? B0 : (region == 1) ? B1 : (region == 2) ? B2 : B3;
    int ldb = (region < 2) ? ldb01 : ldb23;
    const float* Ab = A + (size_t)blockIdx.z * Kc;
    const float* Bb = Bp + (size_t)((bx & 7) * 128) * ldb + (size_t)blockIdx.z * Kc;

    float acc[8][8];
#pragma unroll
    for (int i = 0; i < 8; ++i)
#pragma unroll
        for (int j = 0; j < 8; ++j) acc[i][j] = 0.f;

    for (int k0 = 0; k0 < Kc; k0 += 16) {
#pragma unroll
        for (int it = 0; it < 2; ++it) {
            int f = tid + it * 128;
            int r = f >> 2, q = f & 3;
            float4 vv = *(const float4*)(Ab + (size_t)r * lda + k0 + q * 4);
            As[q * 4 + 0][r] = vv.x; As[q * 4 + 1][r] = vv.y;
            As[q * 4 + 2][r] = vv.z; As[q * 4 + 3][r] = vv.w;
        }
#pragma unroll
        for (int it = 0; it < 4; ++it) {
            int f = tid + it * 128;
            int r = f >> 2, q = f & 3;
            float4 vv = *(const float4*)(Bb + (size_t)r * ldb + k0 + q * 4);
            Bs[q * 4 + 0][r] = vv.x; Bs[q * 4 + 1][r] = vv.y;
            Bs[q * 4 + 2][r] = vv.z; Bs[q * 4 + 3][r] = vv.w;
        }
        __syncthreads();
#pragma unroll
        for (int kk = 0; kk < 16; ++kk) {
            float a[8], b[8];
            *(float4*)(a)     = *(const float4*)&As[kk][trow * 8];
            *(float4*)(a + 4) = *(const float4*)&As[kk][trow * 8 + 4];
            *(float4*)(b)     = *(const float4*)&Bs[kk][tcol * 8];
            *(float4*)(b + 4) = *(const float4*)&Bs[kk][tcol * 8 + 4];
#pragma unroll
            for (int i = 0; i < 8; ++i)
#pragma unroll
                for (int j = 0; j < 8; ++j) acc[i][j] += a[i] * b[j];
        }
        __syncthreads();
    }

    float* Cz = part + (size_t)blockIdx.z * strideCz;
    int m0 = trow * 8;
    int n0g = bx * 128 + tcol * 8;
#pragma unroll
    for (int i = 0; i < 8; ++i) {
        float* crow = Cz + (size_t)(m0 + i) * ldc + n0g;
        *(float4*)(crow)     = make_float4(acc[i][0], acc[i][1], acc[i][2], acc[i][3]);
        *(float4*)(crow + 4) = make_float4(acc[i][4], acc[i][5], acc[i][6], acc[i][7]);
    }
}

// ---------------- FFMA NN GEMM, M=64, split-K, 2-region A/B select ----------------
__global__ void __launch_bounds__(128) k_gemmNN(
    const float* __restrict__ A0, const float* __restrict__ A1, int lda,
    const float* __restrict__ B0, const float* __restrict__ B1, int ldb,
    float* __restrict__ part, int ldc, size_t strideCz, int Kc) {
    __shared__ float As[16][64];
    __shared__ float Bs[16][128];
    int tid = threadIdx.x;
    int trow = tid >> 4;
    int tcol = tid & 15;
    int bx = blockIdx.x;
    int region = bx >> 3;
    const float* A = region ? A1 : A0;
    const float* B = region ? B1 : B0;
    int nl = (bx & 7) * 128;
    int kbase = blockIdx.z * Kc;

    float acc[8][8];
#pragma unroll
    for (int i = 0; i < 8; ++i)
#pragma unroll
        for (int j = 0; j < 8; ++j) acc[i][j] = 0.f;

    for (int k0 = 0; k0 < Kc; k0 += 16) {
#pragma unroll
        for (int it = 0; it < 2; ++it) {
            int f = tid + it * 128;
            int m = f >> 2, q = f & 3;
            float4 av = *(const float4*)(A + (size_t)m * lda + kbase + k0 + q * 4);
            As[q * 4 + 0][m] = av.x; As[q * 4 + 1][m] = av.y;
            As[q * 4 + 2][m] = av.z; As[q * 4 + 3][m] = av.w;
        }
#pragma unroll
        for (int it = 0; it < 4; ++it) {
            int f = tid + it * 128;
            int k = f >> 5, n4 = f & 31;
            *(float4*)&Bs[k][n4 * 4] =
                *(const float4*)(B + (size_t)(kbase + k0 + k) * ldb + nl + n4 * 4);
        }
        __syncthreads();
#pragma unroll
        for (int kk = 0; kk < 16; ++kk) {
            float a[8], b[8];
            *(float4*)(a)     = *(const float4*)&As[kk][trow * 8];
            *(float4*)(a + 4) = *(const float4*)&As[kk][trow * 8 + 4];
            *(float4*)(b)     = *(const float4*)&Bs[kk][tcol * 8];
            *(float4*)(b + 4) = *(const float4*)&Bs[kk][tcol * 8 + 4];
#pragma unroll
            for (int i = 0; i < 8; ++i)
#pragma unroll
                for (int j = 0; j < 8; ++j) acc[i][j] += a[i] * b[j];
        }
        __syncthreads();
    }

    float* Cz = part + (size_t)blockIdx.z * strideCz;
    int m0 = trow * 8;
    int n0g = bx * 128 + tcol * 8;
#pragma unroll
    for (int i = 0; i < 8; ++i) {
        float* crow = Cz + (size_t)(m0 + i) * ldc + n0g;
        *(float4*)(crow)     = make_float4(acc[i][0], acc[i][1], acc[i][2], acc[i][3]);
        *(float4*)(crow + 4) = make_float4(acc[i][4], acc[i][5], acc[i][6], acc[i][7]);
    }
}

// split-K reduce. mode 0: plain. 1: +bias. 2: vctx epilogue (builds Xc/Xv(4-slot)/Xn).
__global__ void k_reduce(const float* __restrict__ part, float* __restrict__ C,
                         int total, int splitk, const float* __restrict__ bias,
                         int mode, const float* __restrict__ v) {
    int idx = blockIdx.x * 256 + threadIdx.x;
    if (idx >= total) return;
    float s = 0.f;
    for (int z = 0; z < splitk; ++z) s += part[(size_t)z * total + idx];
    if (mode == 2) {
        int m = idx >> 10, d = idx & 1023;
        float a = v[idx];
        g_Xc[(size_t)m * 3072 + d] = s;
        float* xv = g_Xv + (size_t)m * 4096;
        xv[d] = a; xv[1024 + d] = s; xv[2048 + d] = a * s; xv[3072 + d] = s - a;
        float* xn = g_Xn + (size_t)m * 2048;
        xn[d] = a; xn[1024 + d] = s;
    } else {
        if (mode == 1) s += bias[idx & 1023];
        C[idx] = s;
    }
}

// ---------------- fused attention: score + masked softmax + ctx aggregation ----------
__global__ void __launch_bounds__(256) k_attn(const int* __restrict__ conn) {
    __shared__ int ke[64];
    __shared__ float sd[64];
    __shared__ float sinv;
    int tid = threadIdx.x;
    int i = blockIdx.x;
    bool rowdir = (blockIdx.y == 0);
    const float* q = g_QQ2 + (size_t)i * 2048 + (rowdir ? 0 : 1024);

    if (tid < 64)
        ke[tid] = rowdir ? conn[i * 64 + tid] : conn[tid * 64 + i];
    __syncthreads();

    int w = tid >> 5, lane = tid & 31;
    for (int jj = w; jj < 64; jj += 8) {
        int k = ke[jj];
        float dot = 0.f;
        if (k >= 0) {
            const float* r = g_relj + (size_t)k * Dm;
#pragma unroll
            for (int d = 0; d < 32; ++d) dot += q[lane + d * 32] * r[lane + d * 32];
#pragma unroll
            for (int off = 16; off; off >>= 1)
                dot += __shfl_down_sync(0xffffffffu, dot, off);
        }
        if (lane == 0) sd[jj] = (k >= 0) ? dot * (1.f / 32.f) : -1e30f;
    }
    __syncthreads();

    if (tid == 0) {
        float m = -1e30f;
        for (int j = 0; j < 64; ++j)
            if (ke[j] >= 0) m = fmaxf(m, sd[j]);
        float sum = 0.f;
        for (int j = 0; j < 64; ++j) {
            float e = (ke[j] >= 0) ? expf(sd[j] - m) : 0.f;
            sd[j] = e; sum += e;
        }
        sinv = 1.f / sum;
    }
    __syncthreads();

    float inv = sinv;
    float* dst = g_Xc + (size_t)i * 3072 + (rowdir ? 1024 : 2048);
#pragma unroll
    for (int dd = 0; dd < 4; ++dd) {
        int d = tid + dd * 256;
        float acc = 0.f;
        for (int j = 0; j < 64; ++j) {
            int k = ke[j];
            if (k >= 0) acc += (sd[j] * inv) * g_relj[(size_t)k * Dm + d];
        }
        dst[d] = acc;
    }
}

// ---------------- host side ----------------
static float* getsym(const void* s) {
    void* p = nullptr;
    cudaGetSymbolAddress(&p, s);
    return (float*)p;
}

extern "C" void kernel_launch(void* const* d_in, const int* in_sizes, int n_in,
                              void* d_out, int out_size) {
    (void)in_sizes; (void)n_in; (void)out_size;
    const float* v        = (const float*)d_in[0];
    const float* rel      = (const float*)d_in[1];
    const int*   conn     = (const int*)d_in[2];
    const int*   eidx     = (const int*)d_in[4];
    const float* W_sub    = (const float*)d_in[5];
    const float* W_obj    = (const float*)d_in[6];
    const float* W_r2s    = (const float*)d_in[7];
    const float* W_r2o    = (const float*)d_in[8];
    const float* W_joint  = (const float*)d_in[9];
    const float* W_ctx    = (const float*)d_in[10];
    const float* W_relup  = (const float*)d_in[11];
    const float* W_reljnt = (const float*)d_in[12];
    const float* W_relctx = (const float*)d_in[13];
    const float* W_node   = (const float*)d_in[14];
    const float* b_node   = (const float*)d_in[15];
    const float* W_factor = (const float*)d_in[16];

    float* out_f   = (float*)d_out;
    float* rel_out = out_f;
    float* v_out   = out_f + (size_t)Ne * Dm;

    float* Xv   = getsym(g_Xv);
    float* vj   = getsym(g_vj);
    float* SO   = getsym(g_SO);
    float* QQ   = getsym(g_QQ);
    float* QQ2  = getsym(g_QQ2);
    float* Xr   = getsym(g_Xr);
    float* rj   = getsym(g_rj);
    float* relj = getsym(g_relj);
    float* XrcB = getsym(g_Xrc2);
    float* Xc   = getsym(g_Xc);
    float* Xn   = getsym(g_Xn);
    float* part = getsym(g_part);
    float* WrB  = getsym(g_WrB);
    float* xrc[2] = {XrcB, XrcB + (size_t)Ne * 2048};

    cudaFuncSetAttribute(k_tgemm<0>, cudaFuncAttributeMaxDynamicSharedMemorySize, SMEM_BYTES);
    cudaFuncSetAttribute(k_tgemm<1>, cudaFuncAttributeMaxDynamicSharedMemorySize, SMEM_BYTES);
    cudaFuncSetAttribute(k_tgemm<2>, cudaFuncAttributeMaxDynamicSharedMemorySize, SMEM_BYTES);
    cudaFuncSetAttribute(k_tgemm<3>, cudaFuncAttributeMaxDynamicSharedMemorySize, SMEM_BYTES);

    // ---- streams + events for graph-capture fork/join (created once) ----
    static cudaStream_t s1 = nullptr, s2 = nullptr;
    static cudaEvent_t evInit, evA[2], evR[2], evAttn0, evWrB, evEnd;
    if (s1 == nullptr) {
        cudaStreamCreateWithFlags(&s1, cudaStreamNonBlocking);
        cudaStreamCreateWithFlags(&s2, cudaStreamNonBlocking);
        cudaEventCreateWithFlags(&evInit, cudaEventDisableTiming);
        cudaEventCreateWithFlags(&evA[0], cudaEventDisableTiming);
        cudaEventCreateWithFlags(&evA[1], cudaEventDisableTiming);
        cudaEventCreateWithFlags(&evR[0], cudaEventDisableTiming);
        cudaEventCreateWithFlags(&evR[1], cudaEventDisableTiming);
        cudaEventCreateWithFlags(&evAttn0, cudaEventDisableTiming);
        cudaEventCreateWithFlags(&evWrB, cudaEventDisableTiming);
        cudaEventCreateWithFlags(&evEnd, cudaEventDisableTiming);
    }
    cudaStream_t s0 = 0;

    k_init<<<1024, 256, 0, s0>>>(v, rel, eidx, xrc[0]);
    cudaEventRecord(evInit, s0);
    cudaStreamWaitEvent(s1, evInit, 0);
    // WrB fold on s2 (only forked from s0 capture origin)
    cudaStreamWaitEvent(s2, evInit, 0);
    k_foldB<<<4096, 256, 0, s2>>>(W_reljnt);
    cudaEventRecord(evWrB, s2);

    for (int t = 0; t < 2; ++t) {
        int Kv = (t == 0) ? 3072 : 4096;   // vj raw K
        int Kr = 3072;                     // rj K (raw t0, folded t1)

        // -------- node chain on s1 --------
        // vj = Xv @ W_joint^T  (raw, split-K 16, FFMA)
        k_gemm<<<dim3(8, 1, 16), 128, 0, s1>>>(Xv, 4096, W_joint, W_joint, W_joint, W_joint,
                                               4096, 4096, part, 1024, 65536, Kv / 16);
        k_reduce<<<256, 256, 0, s1>>>(part, vj, 65536, 16, nullptr, 0, nullptr);
        // SO = vj @ [Ws | Wo]^T  (N=2048, split-K 8) -- relj only needs this
        k_gemm<<<dim3(16, 1, 8), 128, 0, s1>>>(vj, 1024, W_relup, W_relup + 1024,
                                               W_relup, W_relup, 3072, 3072,
                                               part, 2048, 131072, 128);
        k_reduce<<<512, 256, 0, s1>>>(part, SO, 131072, 8, nullptr, 0, nullptr);
        cudaEventRecord(evA[t], s1);
        // QQ = vj @ [Wsub | Wobj]^T
        k_gemm<<<dim3(16, 1, 8), 128, 0, s1>>>(vj, 1024, W_sub, W_obj, W_sub, W_obj,
                                               1024, 1024, part, 2048, 131072, 128);
        k_reduce<<<512, 256, 0, s1>>>(part, QQ, 131072, 8, nullptr, 0, nullptr);
        // QQ2 = [Qs @ W_r2s | Qo @ W_r2o]  (NN)
        k_gemmNN<<<dim3(16, 1, 8), 128, 0, s1>>>(QQ, QQ + 1024, 2048,
                                                 W_r2s, W_r2o, 1024,
                                                 part, 2048, 131072, 128);
        k_reduce<<<512, 256, 0, s1>>>(part, QQ2, 131072, 8, nullptr, 0, nullptr);

        // -------- edge chain on s0 --------
        if (t == 0) {
            // rj = [r,r,r^2] @ W_reljnt^T  (raw, K=3072)
            k_tgemm<3><<<dim3(16, 8), 256, SMEM_BYTES, s0>>>(Xr, 3072, W_reljnt, 4096,
                                                             rj, Kr, nullptr, nullptr, 0);
        } else {
            cudaStreamWaitEvent(s0, evWrB, 0);
            // rj = [r,c,rc] @ WrB^T  (folded, K=3072)
            k_tgemm<3><<<dim3(16, 8), 256, SMEM_BYTES, s0>>>(Xr, 3072, WrB, 3072,
                                                             rj, Kr, nullptr, nullptr, 0);
        }
        cudaStreamWaitEvent(s0, evA[t], 0);
        if (t == 1) cudaStreamWaitEvent(s0, evAttn0, 0);
        k_tgemm<1><<<dim3(16, 8), 256, SMEM_BYTES, s0>>>(rj, 1024, W_relup + 2048, 3072,
                                                         relj, 1024, xrc[t], nullptr, 0);
        cudaEventRecord(evR[t], s0);
        k_tgemm<2><<<dim3(16, 8), 256, SMEM_BYTES, s0>>>(xrc[t], 2048, W_relctx, 2048,
                                                         nullptr, 2048,
                                                         xrc[t ^ 1], rel,
                                                         (t == 0) ? 1 : 2);

        // -------- attn + vctx on s1 --------
        cudaStreamWaitEvent(s1, evR[t], 0);
        k_attn<<<dim3(64, 2), 256, 0, s1>>>(conn);
        if (t == 0) cudaEventRecord(evAttn0, s1);
        k_gemm<<<dim3(8, 1, 16), 128, 0, s1>>>(Xc, 3072, W_ctx, W_ctx, W_ctx, W_ctx,
                                               3072, 3072, part, 1024, 65536, 192);
        k_reduce<<<256, 256, 0, s1>>>(part, nullptr, 65536, 16, nullptr, 2, v);
    }

    // rel_out = [rel, relctx] @ W_factor^T  (s0)
    k_tgemm<0><<<dim3(16, 8), 256, SMEM_BYTES, s0>>>(xrc[0], 2048, W_factor, 2048,
                                                     rel_out, 2048, nullptr, nullptr, 0);

    // v_out = Xn @ W_node^T + b_node  (s1)
    k_gemm<<<dim3(8, 1, 16), 128, 0, s1>>>(Xn, 2048, W_node, W_node, W_node, W_node,
                                           2048, 2048, part, 1024, 65536, 128);
    k_reduce<<<256, 256, 0, s1>>>(part, v_out, 65536, 16, b_node, 1, nullptr);

    // join s1 back into s0
    cudaEventRecord(evEnd, s1);
    cudaStreamWaitEvent(s0, evEnd, 0);
}

// round 15
// speedup vs baseline: 1.1943x; 1.1943x over previous
#include <cuda_runtime.h>
#include <cstdint>

#define Dm 1024
#define Nn 64
#define Ne 1024

// ---------------- scratch (device globals; no allocations allowed) ----------------
__device__ float g_Xv[Nn * 3 * Dm];
__device__ float g_vj[Nn * Dm];
__device__ float g_SOQQ[Nn * 4 * Dm];
__device__ float g_QQ2[Nn * 2 * Dm];
__device__ float g_Xr[Ne * 3 * Dm];
__device__ float g_rj[Ne * Dm];
__device__ float g_relj[Ne * Dm];
__device__ float g_Xrc2[2 * Ne * 2 * Dm];
__device__ float g_Xc[Nn * 3 * Dm];
__device__ float g_Xn[Nn * 2 * Dm];
__device__ float g_part[8 * Nn * 4 * Dm];
__device__ float g_WjA[Dm * 2048];
__device__ float g_WjB[Dm * 3072];
__device__ float g_WrA[Dm * 2048];
__device__ float g_WrB[Dm * 3072];
__device__ int g_src[Ne];
__device__ int g_dst[Ne];

__device__ __forceinline__ uint32_t f2tf32(float x) {
    uint32_t u;
    asm("cvt.rna.tf32.f32 %0, %1;" : "=r"(u) : "f"(x));
    return u;
}
__device__ __forceinline__ float rtf(float x) { return __uint_as_float(f2tf32(x)); }

__device__ __forceinline__ uint32_t smem_u32(const void* p) {
    uint32_t r;
    asm("{ .reg .u64 t; cvta.to.shared.u64 t, %1; cvt.u32.u64 %0, t; }" : "=r"(r) : "l"(p));
    return r;
}

// ---------------- data setup only (s0) ----------------
__global__ void k_initData(const float* __restrict__ v, const float* __restrict__ rel,
                           const int* __restrict__ eidx, float* __restrict__ xrcA) {
    int idx = blockIdx.x * 256 + threadIdx.x;
    int stride = gridDim.x * 256;
    for (int t = idx; t < Ne * Dm; t += stride) {
        int e = t >> 10, d = t & 1023;
        float r = rel[t];
        float* xr = g_Xr + (size_t)e * 2048;
        xr[d] = rtf(r); xr[1024 + d] = rtf(r * r);
        xrcA[(size_t)e * 2048 + d] = rtf(r);
    }
    for (int t = idx; t < Nn * Dm; t += stride) {
        int i = t >> 10, d = t & 1023;
        float a = v[t];
        float* xv = g_Xv + (size_t)i * 2048;
        xv[d] = a; xv[1024 + d] = a * a;
        g_Xc[(size_t)i * 3072 + d] = a;
    }
    for (int t = idx; t < Ne; t += stride) {
        int e = eidx[t];
        g_src[t] = e >> 6;
        g_dst[t] = e & 63;
    }
}

// ---------------- fold vj weights (s1) ----------------
__global__ void k_foldWj(const float* __restrict__ Wj) {
    int idx = blockIdx.x * 256 + threadIdx.x;
    if (idx >= Dm * Dm) return;
    int o = idx >> 10, d = idx & 1023;
    const float* r = Wj + (size_t)o * 4096;
    float w1 = r[d], w2 = r[1024 + d], w3 = r[2048 + d], w4 = r[3072 + d];
    g_WjA[(size_t)o * 2048 + d] = w1 + w2;
    g_WjA[(size_t)o * 2048 + 1024 + d] = w3;
    g_WjB[(size_t)o * 3072 + d] = w1 - w4;
    g_WjB[(size_t)o * 3072 + 1024 + d] = w2 + w4;
    g_WjB[(size_t)o * 3072 + 2048 + d] = w3;
}

// ---------------- fold rj weights (s2) ----------------
__global__ void k_foldWr(const float* __restrict__ Wr) {
    int idx = blockIdx.x * 256 + threadIdx.x;
    if (idx >= Dm * Dm) return;
    int o = idx >> 10, d = idx & 1023;
    const float* r = Wr + (size_t)o * 4096;
    float w1 = r[d], w2 = r[1024 + d], w3 = r[2048 + d], w4 = r[3072 + d];
    g_WrA[(size_t)o * 2048 + d] = rtf(w1 + w2);
    g_WrA[(size_t)o * 2048 + 1024 + d] = rtf(w3);
    g_WrB[(size_t)o * 3072 + d] = rtf(w1 + w4);
    g_WrB[(size_t)o * 3072 + 1024 + d] = rtf(w2 - w4);
    g_WrB[(size_t)o * 3072 + 2048 + d] = rtf(w3);
}

// ======================= tf32 tensor-core NT GEMM (cp.async, BK=32, 3-stage) ======
#define TS 3
#define BK 32
#define APAD 36
#define A_STG (128 * APAD)
#define B_STG (64 * APAD)
#define SMEM_BYTES ((TS * A_STG + TS * B_STG) * 4)

template <int MODE>
__global__ void __launch_bounds__(256) k_tgemm(
    const float* __restrict__ A, int lda,
    const float* __restrict__ B, int ldb,
    float* __restrict__ C, int K,
    float* __restrict__ xrc_w, const float* __restrict__ rel, int flag) {
    extern __shared__ float smem[];
    float* As = smem;
    float* Bs = smem + TS * A_STG;

    int tid = threadIdx.x;
    int lane = tid & 31;
    int w = tid >> 5;
    int wm = (w & 3) * 32;
    int wn = (w >> 2) * 32;
    int gr = lane >> 2;
    int gc = lane & 3;

    const float* Ag = A + (size_t)(blockIdx.y * 128 + (tid >> 1)) * lda + (tid & 1) * 16;
    const float* Bg = B + (size_t)(blockIdx.x * 64 + (tid >> 2)) * ldb + (tid & 3) * 8;
    uint32_t a_dst = smem_u32(&As[(tid >> 1) * APAD + (tid & 1) * 16]);
    uint32_t b_dst = smem_u32(&Bs[(tid >> 2) * APAD + (tid & 3) * 8]);

    int niter = K >> 5;

#define ISSUE_STAGE(s, k0)                                                                   \
    do {                                                                                     \
        uint32_t ad = a_dst + (uint32_t)(s) * (A_STG * 4);                                   \
        const float* ap = Ag + (k0);                                                         \
        asm volatile("cp.async.cg.shared.global [%0], [%1], 16;" :: "r"(ad), "l"(ap));       \
        asm volatile("cp.async.cg.shared.global [%0], [%1], 16;" :: "r"(ad + 16), "l"(ap + 4)); \
        asm volatile("cp.async.cg.shared.global [%0], [%1], 16;" :: "r"(ad + 32), "l"(ap + 8)); \
        asm volatile("cp.async.cg.shared.global [%0], [%1], 16;" :: "r"(ad + 48), "l"(ap + 12)); \
        uint32_t bd = b_dst + (uint32_t)(s) * (B_STG * 4);                                   \
        const float* bp = Bg + (k0);                                                         \
        asm volatile("cp.async.cg.shared.global [%0], [%1], 16;" :: "r"(bd), "l"(bp));       \
        asm volatile("cp.async.cg.shared.global [%0], [%1], 16;" :: "r"(bd + 16), "l"(bp + 4)); \
    } while (0)

    ISSUE_STAGE(0, 0);
    asm volatile("cp.async.commit_group;");
    ISSUE_STAGE(1, BK);
    asm volatile("cp.async.commit_group;");

    float c[2][4][4];
#pragma unroll
    for (int mt = 0; mt < 2; ++mt)
#pragma unroll
        for (int nt = 0; nt < 4; ++nt)
#pragma unroll
            for (int q = 0; q < 4; ++q) c[mt][nt][q] = 0.f;

    const uint32_t* Asu = reinterpret_cast<const uint32_t*>(As);
    const float* Bsf = Bs;

    int s = 0;
    for (int i = 0; i < niter; ++i) {
        asm volatile("cp.async.wait_group 1;" ::: "memory");
        __syncthreads();
        {
            int nx = i + 2;
            if (nx < niter) {
                int sn = s + 2; if (sn >= TS) sn -= TS;
                ISSUE_STAGE(sn, nx * BK);
            }
            asm volatile("cp.async.commit_group;");
        }
        int base_a = s * A_STG;
        int base_b = s * B_STG;
#pragma unroll
        for (int half = 0; half < 2; ++half) {
            uint32_t a[2][2][4], b[2][4][2];
#pragma unroll
            for (int ks = 0; ks < 2; ++ks) {
                int kb = half * 16 + ks * 8 + gc;
#pragma unroll
                for (int mt = 0; mt < 2; ++mt) {
                    int m0 = wm + mt * 16 + gr;
                    a[ks][mt][0] = Asu[base_a + m0 * APAD + kb];
                    a[ks][mt][1] = Asu[base_a + (m0 + 8) * APAD + kb];
                    a[ks][mt][2] = Asu[base_a + m0 * APAD + kb + 4];
                    a[ks][mt][3] = Asu[base_a + (m0 + 8) * APAD + kb + 4];
                }
#pragma unroll
                for (int nt = 0; nt < 4; ++nt) {
                    int n0 = wn + nt * 8 + gr;
                    b[ks][nt][0] = f2tf32(Bsf[base_b + n0 * APAD + kb]);
                    b[ks][nt][1] = f2tf32(Bsf[base_b + n0 * APAD + kb + 4]);
                }
            }
#pragma unroll
            for (int ks = 0; ks < 2; ++ks)
#pragma unroll
                for (int mt = 0; mt < 2; ++mt)
#pragma unroll
                    for (int nt = 0; nt < 4; ++nt) {
                        asm volatile(
                            "mma.sync.aligned.m16n8k8.row.col.f32.tf32.tf32.f32 "
                            "{%0,%1,%2,%3}, {%4,%5,%6,%7}, {%8,%9}, {%0,%1,%2,%3};"
                            : "+f"(c[mt][nt][0]), "+f"(c[mt][nt][1]),
                              "+f"(c[mt][nt][2]), "+f"(c[mt][nt][3])
                            : "r"(a[ks][mt][0]), "r"(a[ks][mt][1]),
                              "r"(a[ks][mt][2]), "r"(a[ks][mt][3]),
                              "r"(b[ks][nt][0]), "r"(b[ks][nt][1]));
                    }
        }
        if (++s >= TS) s -= TS;
    }
#undef ISSUE_STAGE

    int mbase = blockIdx.y * 128 + wm;
    int nbase = blockIdx.x * 64 + wn;
#pragma unroll
    for (int mt = 0; mt < 2; ++mt) {
#pragma unroll
        for (int half = 0; half < 2; ++half) {
            int row = mbase + mt * 16 + gr + half * 8;
#pragma unroll
            for (int nt = 0; nt < 4; ++nt) {
                int col = nbase + nt * 8 + 2 * gc;
                float vx = c[mt][nt][half * 2 + 0];
                float vy = c[mt][nt][half * 2 + 1];
                if (MODE == 0) {
                    *(float2*)(C + (size_t)row * 1024 + col) = make_float2(vx, vy);
                } else if (MODE == 3) {
                    *(float2*)(C + (size_t)row * 1024 + col) = make_float2(rtf(vx), rtf(vy));
                } else if (MODE == 1) {
                    const float* sp = g_SOQQ + (size_t)g_src[row] * 4096 + col;
                    const float* op = g_SOQQ + (size_t)g_dst[row] * 4096 + 1024 + col;
                    vx += sp[0] + op[0];
                    vy += sp[1] + op[1];
                    *(float2*)(C + (size_t)row * 1024 + col) = make_float2(vx, vy);
                    *(float2*)(xrc_w + (size_t)row * 2048 + 1024 + col) =
                        make_float2(rtf(vx), rtf(vy));
                } else {  // MODE 2
                    float2 rv = *(const float2*)(rel + (size_t)row * 1024 + col);
                    if (flag == 1) {
                        *(float2*)(xrc_w + (size_t)row * 2048 + col) =
                            make_float2(rtf(vx), rtf(vy));
                        float* xr = g_Xr + (size_t)row * 3072;
                        *(float2*)(xr + col)        = make_float2(rtf(rv.x), rtf(rv.y));
                        *(float2*)(xr + 1024 + col) = make_float2(rtf(vx), rtf(vy));
                        *(float2*)(xr + 2048 + col) =
                            make_float2(rtf(rv.x * vx), rtf(rv.y * vy));
                    } else {
                        *(float2*)(xrc_w + (size_t)row * 2048 + col) =
                            make_float2(rtf(rv.x), rtf(rv.y));
                        *(float2*)(xrc_w + (size_t)row * 2048 + 1024 + col) =
                            make_float2(rtf(vx), rtf(vy));
                    }
                }
            }
        }
    }
}

// ---------------- FFMA NT GEMM, M=64, split-K, 4-region B select ----------------
__global__ void __launch_bounds__(128) k_gemm(
    const float* __restrict__ A, int lda,
    const float* __restrict__ B0, const float* __restrict__ B1,
    const float* __restrict__ B2, const float* __restrict__ B3,
    int ldb01, int ldb23,
    float* __restrict__ part, int ldc, size_t strideCz, int Kc) {
    __shared__ float As[16][64];
    __shared__ float Bs[16][128];
    int tid = threadIdx.x;
    int trow = tid >> 4;
    int tcol = tid & 15;
    int bx = blockIdx.x;
    int region = bx >> 3;
    const float* Bp = (region == 0) ? B0 : (region == 1) ? B1 : (region == 2) ? B2 : B3;
    int ldb = (region < 2) ? ldb01 : ldb23;
    const float* Ab = A + (size_t)blockIdx.z * Kc;
    const float* Bb = Bp + (size_t)((bx & 7) * 128) * ldb + (size_t)blockIdx.z * Kc;

    float acc[8][8];
#pragma unroll
    for (int i = 0; i < 8; ++i)
#pragma unroll
        for (int j = 0; j < 8; ++j) acc[i][j] = 0.f;

    for (int k0 = 0; k0 < Kc; k0 += 16) {
#pragma unroll
        for (int it = 0; it < 2; ++it) {
            int f = tid + it * 128;
            int r = f >> 2, q = f & 3;
            float4 vv = *(const float4*)(Ab + (size_t)r * lda + k0 + q * 4);
            As[q * 4 + 0][r] = vv.x; As[q * 4 + 1][r] = vv.y;
            As[q * 4 + 2][r] = vv.z; As[q * 4 + 3][r] = vv.w;
        }
#pragma unroll
        for (int it = 0; it < 4; ++it) {
            int f = tid + it * 128;
            int r = f >> 2, q = f & 3;
            float4 vv = *(const float4*)(Bb + (size_t)r * ldb + k0 + q * 4);
            Bs[q * 4 + 0][r] = vv.x; Bs[q * 4 + 1][r] = vv.y;
            Bs[q * 4 + 2][r] = vv.z; Bs[q * 4 + 3][r] = vv.w;
        }
        __syncthreads();
#pragma unroll
        for (int kk = 0; kk < 16; ++kk) {
            float a[8], b[8];
            *(float4*)(a)     = *(const float4*)&As[kk][trow * 8];
            *(float4*)(a + 4) = *(const float4*)&As[kk][trow * 8 + 4];
            *(float4*)(b)     = *(const float4*)&Bs[kk][tcol * 8];
            *(float4*)(b + 4) = *(const float4*)&Bs[kk][tcol * 8 + 4];
#pragma unroll
            for (int i = 0; i < 8; ++i)
#pragma unroll
                for (int j = 0; j < 8; ++j) acc[i][j] += a[i] * b[j];
        }
        __syncthreads();
    }

    float* Cz = part + (size_t)blockIdx.z * strideCz;
    int m0 = trow * 8;
    int n0g = bx * 128 + tcol * 8;
#pragma unroll
    for (int i = 0; i < 8; ++i) {
        float* crow = Cz + (size_t)(m0 + i) * ldc + n0g;
        *(float4*)(crow)     = make_float4(acc[i][0], acc[i][1], acc[i][2], acc[i][3]);
        *(float4*)(crow + 4) = make_float4(acc[i][4], acc[i][5], acc[i][6], acc[i][7]);
    }
}

// ---------------- FFMA NN GEMM, M=64, split-K, 2-region A/B select ----------------
__global__ void __launch_bounds__(128) k_gemmNN(
    const float* __restrict__ A0, const float* __restrict__ A1, int lda,
    const float* __restrict__ B0, const float* __restrict__ B1, int ldb,
    float* __restrict__ part, int ldc, size_t strideCz, int Kc) {
    __shared__ float As[16][64];
    __shared__ float Bs[16][128];
    int tid = threadIdx.x;
    int trow = tid >> 4;
    int tcol = tid & 15;
    int bx = blockIdx.x;
    int region = bx >> 3;
    const float* A = region ? A1 : A0;
    const float* B = region ? B1 : B0;
    int nl = (bx & 7) * 128;
    int kbase = blockIdx.z * Kc;

    float acc[8][8];
#pragma unroll
    for (int i = 0; i < 8; ++i)
#pragma unroll
        for (int j = 0; j < 8; ++j) acc[i][j] = 0.f;

    for (int k0 = 0; k0 < Kc; k0 += 16) {
#pragma unroll
        for (int it = 0; it < 2; ++it) {
            int f = tid + it * 128;
            int m = f >> 2, q = f & 3;
            float4 av = *(const float4*)(A + (size_t)m * lda + kbase + k0 + q * 4);
            As[q * 4 + 0][m] = av.x; As[q * 4 + 1][m] = av.y;
            As[q * 4 + 2][m] = av.z; As[q * 4 + 3][m] = av.w;
        }
#pragma unroll
        for (int it = 0; it < 4; ++it) {
            int f = tid + it * 128;
            int k = f >> 5, n4 = f & 31;
            *(float4*)&Bs[k][n4 * 4] =
                *(const float4*)(B + (size_t)(kbase + k0 + k) * ldb + nl + n4 * 4);
        }
        __syncthreads();
#pragma unroll
        for (int kk = 0; kk < 16; ++kk) {
            float a[8], b[8];
            *(float4*)(a)     = *(const float4*)&As[kk][trow * 8];
            *(float4*)(a + 4) = *(const float4*)&As[kk][trow * 8 + 4];
            *(float4*)(b)     = *(const float4*)&Bs[kk][tcol * 8];
            *(float4*)(b + 4) = *(const float4*)&Bs[kk][tcol * 8 + 4];
#pragma unroll
            for (int i = 0; i < 8; ++i)
#pragma unroll
                for (int j = 0; j < 8; ++j) acc[i][j] += a[i] * b[j];
        }
        __syncthreads();
    }

    float* Cz = part + (size_t)blockIdx.z * strideCz;
    int m0 = trow * 8;
    int n0g = bx * 128 + tcol * 8;
#pragma unroll
    for (int i = 0; i < 8; ++i) {
        float* crow = Cz + (size_t)(m0 + i) * ldc + n0g;
        *(float4*)(crow)     = make_float4(acc[i][0], acc[i][1], acc[i][2], acc[i][3]);
        *(float4*)(crow + 4) = make_float4(acc[i][4], acc[i][5], acc[i][6], acc[i][7]);
    }
}

// split-K reduce. mode 0: plain. 1: +bias. 2: vctx epilogue (builds Xc/Xv/Xn).
__global__ void k_reduce(const float* __restrict__ part, float* __restrict__ C,
                         int total, int splitk, const float* __restrict__ bias,
                         int mode, const float* __restrict__ v) {
    int idx = blockIdx.x * 256 + threadIdx.x;
    if (idx >= total) return;
    float s = 0.f;
    for (int z = 0; z < splitk; ++z) s += part[(size_t)z * total + idx];
    if (mode == 2) {
        int m = idx >> 10, d = idx & 1023;
        float a = v[idx];
        g_Xc[(size_t)m * 3072 + d] = s;
        float* xv = g_Xv + (size_t)m * 3072;
        xv[d] = a; xv[1024 + d] = s; xv[2048 + d] = a * s;
        float* xn = g_Xn + (size_t)m * 2048;
        xn[d] = a; xn[1024 + d] = s;
    } else {
        if (mode == 1) s += bias[idx & 1023];
        C[idx] = s;
    }
}

// ---------------- fused attention: score + masked softmax + ctx aggregation ----------
__global__ void __launch_bounds__(256) k_attn(const int* __restrict__ conn) {
    __shared__ int ke[64];
    __shared__ float sd[64];
    __shared__ float sinv;
    int tid = threadIdx.x;
    int i = blockIdx.x;
    bool rowdir = (blockIdx.y == 0);
    const float* q = g_QQ2 + (size_t)i * 2048 + (rowdir ? 0 : 1024);

    if (tid < 64)
        ke[tid] = rowdir ? conn[i * 64 + tid] : conn[tid * 64 + i];
    __syncthreads();

    int w = tid >> 5, lane = tid & 31;
    for (int jj = w; jj < 64; jj += 8) {
        int k = ke[jj];
        float dot = 0.f;
        if (k >= 0) {
            const float* r = g_relj + (size_t)k * Dm;
#pragma unroll
            for (int d = 0; d < 32; ++d) dot += q[lane + d * 32] * r[lane + d * 32];
#pragma unroll
            for (int off = 16; off; off >>= 1)
                dot += __shfl_down_sync(0xffffffffu, dot, off);
        }
        if (lane == 0) sd[jj] = (k >= 0) ? dot * (1.f / 32.f) : -1e30f;
    }
    __syncthreads();

    if (tid == 0) {
        float m = -1e30f;
        for (int j = 0; j < 64; ++j)
            if (ke[j] >= 0) m = fmaxf(m, sd[j]);
        float sum = 0.f;
        for (int j = 0; j < 64; ++j) {
            float e = (ke[j] >= 0) ? expf(sd[j] - m) : 0.f;
            sd[j] = e; sum += e;
        }
        sinv = 1.f / sum;
    }
    __syncthreads();

    float inv = sinv;
    float* dst = g_Xc + (size_t)i * 3072 + (rowdir ? 1024 : 2048);
#pragma unroll
    for (int dd = 0; dd < 4; ++dd) {
        int d = tid + dd * 256;
        float acc = 0.f;
        for (int j = 0; j < 64; ++j) {
            int k = ke[j];
            if (k >= 0) acc += (sd[j] * inv) * g_relj[(size_t)k * Dm + d];
        }
        dst[d] = acc;
    }
}

// ---------------- host side ----------------
static float* getsym(const void* s) {
    void* p = nullptr;
    cudaGetSymbolAddress(&p, s);
    return (float*)p;
}

extern "C" void kernel_launch(void* const* d_in, const int* in_sizes, int n_in,
                              void* d_out, int out_size) {
    (void)in_sizes; (void)n_in; (void)out_size;
    const float* v        = (const float*)d_in[0];
    const float* rel      = (const float*)d_in[1];
    const int*   conn     = (const int*)d_in[2];
    const int*   eidx     = (const int*)d_in[4];
    const float* W_sub    = (const float*)d_in[5];
    const float* W_obj    = (const float*)d_in[6];
    const float* W_r2s    = (const float*)d_in[7];
    const float* W_r2o    = (const float*)d_in[8];
    const float* W_joint  = (const float*)d_in[9];
    const float* W_ctx    = (const float*)d_in[10];
    const float* W_relup  = (const float*)d_in[11];
    const float* W_reljnt = (const float*)d_in[12];
    const float* W_relctx = (const float*)d_in[13];
    const float* W_node   = (const float*)d_in[14];
    const float* b_node   = (const float*)d_in[15];
    const float* W_factor = (const float*)d_in[16];

    float* out_f   = (float*)d_out;
    float* rel_out = out_f;
    float* v_out   = out_f + (size_t)Ne * Dm;

    float* Xv   = getsym(g_Xv);
    float* vj   = getsym(g_vj);
    float* SOQQ = getsym(g_SOQQ);
    float* QQ2  = getsym(g_QQ2);
    float* Xr   = getsym(g_Xr);
    float* rj   = getsym(g_rj);
    float* relj = getsym(g_relj);
    float* XrcB = getsym(g_Xrc2);
    float* Xc   = getsym(g_Xc);
    float* Xn   = getsym(g_Xn);
    float* part = getsym(g_part);
    float* WjA  = getsym(g_WjA);
    float* WjB  = getsym(g_WjB);
    float* WrA  = getsym(g_WrA);
    float* WrB  = getsym(g_WrB);
    float* xrc[2] = {XrcB, XrcB + (size_t)Ne * 2048};

    cudaFuncSetAttribute(k_tgemm<0>, cudaFuncAttributeMaxDynamicSharedMemorySize, SMEM_BYTES);
    cudaFuncSetAttribute(k_tgemm<1>, cudaFuncAttributeMaxDynamicSharedMemorySize, SMEM_BYTES);
    cudaFuncSetAttribute(k_tgemm<2>, cudaFuncAttributeMaxDynamicSharedMemorySize, SMEM_BYTES);
    cudaFuncSetAttribute(k_tgemm<3>, cudaFuncAttributeMaxDynamicSharedMemorySize, SMEM_BYTES);

    // ---- streams + events for graph-capture fork/join (created once) ----
    static cudaStream_t s1 = nullptr, s2 = nullptr;
    static cudaEvent_t evStart, evInit, evWr, evA[2], evR[2], evAttn0, evEnd, evEnd2;
    if (s1 == nullptr) {
        cudaStreamCreateWithFlags(&s1, cudaStreamNonBlocking);
        cudaStreamCreateWithFlags(&s2, cudaStreamNonBlocking);
        cudaEventCreateWithFlags(&evStart, cudaEventDisableTiming);
        cudaEventCreateWithFlags(&evInit, cudaEventDisableTiming);
        cudaEventCreateWithFlags(&evWr, cudaEventDisableTiming);
        cudaEventCreateWithFlags(&evA[0], cudaEventDisableTiming);
        cudaEventCreateWithFlags(&evA[1], cudaEventDisableTiming);
        cudaEventCreateWithFlags(&evR[0], cudaEventDisableTiming);
        cudaEventCreateWithFlags(&evR[1], cudaEventDisableTiming);
        cudaEventCreateWithFlags(&evAttn0, cudaEventDisableTiming);
        cudaEventCreateWithFlags(&evEnd, cudaEventDisableTiming);
        cudaEventCreateWithFlags(&evEnd2, cudaEventDisableTiming);
    }
    cudaStream_t s0 = 0;

    // fork all three streams at the very start
    cudaEventRecord(evStart, s0);
    cudaStreamWaitEvent(s1, evStart, 0);
    cudaStreamWaitEvent(s2, evStart, 0);

    // s0: data setup; s1: vj-weight fold; s2: rj-weight fold — all concurrent
    k_initData<<<1024, 256, 0, s0>>>(v, rel, eidx, xrc[0]);
    cudaEventRecord(evInit, s0);
    k_foldWj<<<4096, 256, 0, s1>>>(W_joint);
    cudaStreamWaitEvent(s1, evInit, 0);   // vj needs Xv from initData
    k_foldWr<<<4096, 256, 0, s2>>>(W_reljnt);
    cudaEventRecord(evWr, s2);
    cudaStreamWaitEvent(s0, evWr, 0);     // rj0 needs WrA (fold ~<= initData time)

    for (int t = 0; t < 2; ++t) {
        int Kx = (t == 0) ? 2048 : 3072;
        const float* Wj = (t == 0) ? WjA : WjB;
        const float* Wr = (t == 0) ? WrA : WrB;

        // -------- node chain on s1 --------
        k_gemm<<<dim3(8, 1, 16), 128, 0, s1>>>(Xv, Kx, Wj, Wj, Wj, Wj,
                                               Kx, Kx, part, 1024, 65536, Kx / 16);
        k_reduce<<<256, 256, 0, s1>>>(part, vj, 65536, 16, nullptr, 0, nullptr);
        if (t == 1) cudaStreamWaitEvent(s1, evR[0], 0);
        k_gemm<<<dim3(32, 1, 8), 128, 0, s1>>>(vj, 1024, W_relup, W_relup + 1024,
                                               W_sub, W_obj, 3072, 1024,
                                               part, 4096, 262144, 128);
        k_reduce<<<1024, 256, 0, s1>>>(part, SOQQ, 262144, 8, nullptr, 0, nullptr);
        cudaEventRecord(evA[t], s1);
        k_gemmNN<<<dim3(16, 1, 8), 128, 0, s1>>>(SOQQ + 2048, SOQQ + 3072, 4096,
                                                 W_r2s, W_r2o, 1024,
                                                 part, 2048, 131072, 128);
        k_reduce<<<512, 256, 0, s1>>>(part, QQ2, 131072, 8, nullptr, 0, nullptr);

        // -------- edge chain on s0 --------
        k_tgemm<3><<<dim3(16, 8), 256, SMEM_BYTES, s0>>>(Xr, Kx, Wr, Kx, rj, Kx,
                                                         nullptr, nullptr, 0);
        cudaStreamWaitEvent(s0, evA[t], 0);
        if (t == 1) cudaStreamWaitEvent(s0, evAttn0, 0);
        k_tgemm<1><<<dim3(16, 8), 256, SMEM_BYTES, s0>>>(rj, 1024, W_relup + 2048, 3072,
                                                         relj, 1024, xrc[t], nullptr, 0);
        cudaEventRecord(evR[t], s0);
        k_tgemm<2><<<dim3(16, 8), 256, SMEM_BYTES, s0>>>(xrc[t], 2048, W_relctx, 2048,
                                                         nullptr, 2048,
                                                         xrc[t ^ 1], rel,
                                                         (t == 0) ? 1 : 2);

        // -------- attn + vctx on s1 --------
        cudaStreamWaitEvent(s1, evR[t], 0);
        k_attn<<<dim3(64, 2), 256, 0, s1>>>(conn);
        if (t == 0) cudaEventRecord(evAttn0, s1);
        k_gemm<<<dim3(8, 1, 16), 128, 0, s1>>>(Xc, 3072, W_ctx, W_ctx, W_ctx, W_ctx,
                                               3072, 3072, part, 1024, 65536, 192);
        k_reduce<<<256, 256, 0, s1>>>(part, nullptr, 65536, 16, nullptr, 2, v);
    }

    // rel_out = [rel, relctx] @ W_factor^T  (s0)
    k_tgemm<0><<<dim3(16, 8), 256, SMEM_BYTES, s0>>>(xrc[0], 2048, W_factor, 2048,
                                                     rel_out, 2048, nullptr, nullptr, 0);

    // v_out = Xn @ W_node^T + b_node  (s1)
    k_gemm<<<dim3(8, 1, 16), 128, 0, s1>>>(Xn, 2048, W_node, W_node, W_node, W_node,
                                           2048, 2048, part, 1024, 65536, 128);
    k_reduce<<<256, 256, 0, s1>>>(part, v_out, 65536, 16, b_node, 1, nullptr);

    // join s1 and s2 back into s0
    cudaEventRecord(evEnd, s1);
    cudaStreamWaitEvent(s0, evEnd, 0);
    cudaEventRecord(evEnd2, s2);
    cudaStreamWaitEvent(s0, evEnd2, 0);
}